// round 9
// baseline (speedup 1.0000x reference)
#include <cuda_runtime.h>
#include <math.h>
#include <stdint.h>

#define DM   1024
#define DI   2048
#define DTR  64
#define NS   16
#define BB   4
#define LL   1024
#define NT   (BB*LL)

// ---------------- scratch ----------------------------------------------------
__device__ __align__(16) float g_xr  [(size_t)NT * 2 * DI];
__device__ __align__(16) float g_xs  [(size_t)NT * DI];
__device__ __align__(16) float g_xdbl[(size_t)NT * 96];
__device__ __align__(16) float g_delta[(size_t)NT * DI];
__device__ __align__(16) float g_yg  [(size_t)NT * DI];
__device__ __align__(16) float g_xa  [(size_t)NT * DM];
__device__ __align__(16) float g_wi  [(size_t)2 * DI * DM];
__device__ __align__(16) float g_wx  [(size_t)96 * DI];
__device__ __align__(16) float g_wdt [(size_t)DI * DTR];
__device__ __align__(16) float g_wo  [(size_t)DM * DI];

// ---------------- helpers -----------------------------------------------------
__device__ __forceinline__ float ex2_approx(float x) {
    float y; asm("ex2.approx.f32 %0, %1;" : "=f"(y) : "f"(x)); return y;
}
__device__ __forceinline__ float tf32_rn(float x) {
    float r; asm("cvt.rna.tf32.f32 %0, %1;" : "=f"(r) : "f"(x)); return r;
}
__device__ __forceinline__ void mma_tf32(float* c, const uint32_t* a, const uint32_t* b) {
    asm volatile(
        "mma.sync.aligned.m16n8k8.row.col.f32.tf32.tf32.f32 "
        "{%0,%1,%2,%3}, {%4,%5,%6,%7}, {%8,%9}, {%0,%1,%2,%3};"
        : "+f"(c[0]), "+f"(c[1]), "+f"(c[2]), "+f"(c[3])
        : "r"(a[0]), "r"(a[1]), "r"(a[2]), "r"(a[3]), "r"(b[0]), "r"(b[1]));
}

// ---------------- TF32 mma.sync GEMM:  C[M,N] = A[M,K] * B[N,K]^T -------------
// BM=BN=128, BK=32, 4-stage cp.async, 256 thr, warp tile 32x64 (exact R3 frame).
// ONE change vs R3: k8 fragment loads are software-pipelined (prefetch k8+1
// while k8's MMAs issue). Per-element accumulation order unchanged.
// EPI: 0 none, 1 softplus(x+bias[n]), 3 atomicAdd (split-K; NGUARD=valid N)
template<int EPI, int NGUARD>
__global__ void __launch_bounds__(256, 1) gemm_mma(
    const float* __restrict__ A, const float* __restrict__ B,
    const float* __restrict__ bias, float* __restrict__ C,
    int K, int lda, int ldb, int ldc)
{
    constexpr int ST = 4;
    constexpr int P  = 36;             // smem row pitch (floats)
    constexpr int TILE = 128 * P;      // floats per stage per operand
    extern __shared__ float sm[];
    float* As = sm;
    float* Bs = sm + ST * TILE;

    const int tid  = threadIdx.x;
    const int wid  = tid >> 5, lane = tid & 31;
    const int g    = lane >> 2, q = lane & 3;
    const int bm   = blockIdx.y * 128;
    const int bn   = blockIdx.x * 128;
    const int T    = K >> 5;
    const int mbase = (wid & 3) * 32;
    const int nbase = (wid >> 2) * 64;

    const float* Ab = A + (size_t)bm * lda + (size_t)blockIdx.z * K;
    const float* Bb = B + (size_t)bn * ldb + (size_t)blockIdx.z * K;

    auto load_tile = [&](int st, int t) {
        float* as = As + st * TILE;
        float* bs = Bs + st * TILE;
        #pragma unroll
        for (int i = 0; i < 4; ++i) {
            int c = tid + i * 256;
            int r = c >> 3, col = (c & 7) * 4;
            const float* src = Ab + (size_t)r * lda + t * 32 + col;
            uint32_t dst = (uint32_t)__cvta_generic_to_shared(as + r * P + col);
            asm volatile("cp.async.cg.shared.global [%0], [%1], 16;"
                         :: "r"(dst), "l"(src));
        }
        #pragma unroll
        for (int i = 0; i < 4; ++i) {
            int c = tid + i * 256;
            int r = c >> 3, col = (c & 7) * 4;
            uint32_t dst = (uint32_t)__cvta_generic_to_shared(bs + r * P + col);
            if (NGUARD && (bn + r) >= NGUARD) {
                asm volatile("cp.async.cg.shared.global [%0], [%1], 16, 0;"
                             :: "r"(dst), "l"(Bb));
            } else {
                const float* src = Bb + (size_t)r * ldb + t * 32 + col;
                asm volatile("cp.async.cg.shared.global [%0], [%1], 16;"
                             :: "r"(dst), "l"(src));
            }
        }
    };

    float c[2][8][4];
    #pragma unroll
    for (int t = 0; t < 2; ++t)
        #pragma unroll
        for (int j = 0; j < 8; ++j)
            #pragma unroll
            for (int i = 0; i < 4; ++i) c[t][j][i] = 0.f;

    #pragma unroll
    for (int s = 0; s < ST - 1; ++s) {
        if (s < T) load_tile(s, s);
        asm volatile("cp.async.commit_group;");
    }

    for (int t = 0; t < T; ++t) {
        asm volatile("cp.async.wait_group 2;");
        __syncthreads();
        const int st = t & 3;
        const float* as0 = As + st * TILE;
        const float* bs0 = Bs + st * TILE;

        uint32_t a[2][2][4], b[2][8][2];
        // prefetch fragments for k8 = 0
        {
            const int k0 = q;
            #pragma unroll
            for (int tt = 0; tt < 2; ++tt) {
                const float* ap = as0 + (mbase + tt * 16 + g) * P + k0;
                a[0][tt][0] = __float_as_uint(ap[0]);
                a[0][tt][1] = __float_as_uint(ap[8 * P]);
                a[0][tt][2] = __float_as_uint(ap[4]);
                a[0][tt][3] = __float_as_uint(ap[8 * P + 4]);
            }
            #pragma unroll
            for (int j = 0; j < 8; ++j) {
                const float* bp = bs0 + (nbase + j * 8 + g) * P + k0;
                b[0][j][0] = __float_as_uint(bp[0]);
                b[0][j][1] = __float_as_uint(bp[4]);
            }
        }
        #pragma unroll
        for (int k8 = 0; k8 < 4; ++k8) {
            const int cur = k8 & 1, nxt = cur ^ 1;
            if (k8 < 3) {
                const int k0n = (k8 + 1) * 8 + q;
                #pragma unroll
                for (int tt = 0; tt < 2; ++tt) {
                    const float* ap = as0 + (mbase + tt * 16 + g) * P + k0n;
                    a[nxt][tt][0] = __float_as_uint(ap[0]);
                    a[nxt][tt][1] = __float_as_uint(ap[8 * P]);
                    a[nxt][tt][2] = __float_as_uint(ap[4]);
                    a[nxt][tt][3] = __float_as_uint(ap[8 * P + 4]);
                }
                #pragma unroll
                for (int j = 0; j < 8; ++j) {
                    const float* bp = bs0 + (nbase + j * 8 + g) * P + k0n;
                    b[nxt][j][0] = __float_as_uint(bp[0]);
                    b[nxt][j][1] = __float_as_uint(bp[4]);
                }
            }
            #pragma unroll
            for (int tt = 0; tt < 2; ++tt)
                #pragma unroll
                for (int j = 0; j < 8; ++j)
                    mma_tf32(c[tt][j], a[cur][tt], b[cur][j]);
        }
        const int kt = t + ST - 1;
        if (kt < T) load_tile(kt & 3, kt);
        asm volatile("cp.async.commit_group;");
    }

    // epilogue
    #pragma unroll
    for (int tt = 0; tt < 2; ++tt) {
        const int r0 = bm + mbase + tt * 16 + g;
        #pragma unroll
        for (int j = 0; j < 8; ++j) {
            const int col = bn + nbase + j * 8 + q * 2;
            float v0 = c[tt][j][0], v1 = c[tt][j][1];
            float v2 = c[tt][j][2], v3 = c[tt][j][3];
            if (EPI == 1) {
                float b0 = bias[col], b1 = bias[col + 1];
                v0 += b0; v1 += b1; v2 += b0; v3 += b1;
                v0 = (v0 > 20.f) ? v0 : log1pf(__expf(v0));
                v1 = (v1 > 20.f) ? v1 : log1pf(__expf(v1));
                v2 = (v2 > 20.f) ? v2 : log1pf(__expf(v2));
                v3 = (v3 > 20.f) ? v3 : log1pf(__expf(v3));
            }
            if (EPI == 3) {
                if (!NGUARD || col < NGUARD) {
                    atomicAdd(&C[(size_t)r0 * ldc + col], v0);
                    atomicAdd(&C[(size_t)r0 * ldc + col + 1], v1);
                    atomicAdd(&C[(size_t)(r0 + 8) * ldc + col], v2);
                    atomicAdd(&C[(size_t)(r0 + 8) * ldc + col + 1], v3);
                }
            } else {
                float2 p0 = make_float2(v0, v1);
                float2 p1 = make_float2(v2, v3);
                *(float2*)&C[(size_t)r0 * ldc + col] = p0;
                *(float2*)&C[(size_t)(r0 + 8) * ldc + col] = p1;
            }
        }
    }
}

// ---------------- tf32 rounding copy ------------------------------------------
__global__ void round_tf32_kernel(const float* __restrict__ src,
                                  float* __restrict__ dst, int n4)
{
    int i = blockIdx.x * blockDim.x + threadIdx.x;
    if (i < n4) {
        float4 v = ((const float4*)src)[i];
        v.x = tf32_rn(v.x); v.y = tf32_rn(v.y);
        v.z = tf32_rn(v.z); v.w = tf32_rn(v.w);
        ((float4*)dst)[i] = v;
    }
}

// ---------------- causal depthwise conv1d (width 4) + SiLU (+tf32) ------------
__global__ void conv_silu_kernel(const float* __restrict__ conv_w,
                                 const float* __restrict__ conv_b)
{
    int idx = blockIdx.x * blockDim.x + threadIdx.x;
    int d  = idx & (DI - 1);
    int bl = idx >> 11;
    int l  = bl & (LL - 1);
    float w0 = conv_w[d * 4 + 0], w1 = conv_w[d * 4 + 1];
    float w2 = conv_w[d * 4 + 2], w3 = conv_w[d * 4 + 3];
    const float* col = g_xr + (size_t)bl * (2 * DI) + d;
    float s = conv_b[d];
    if (l >= 3) s = fmaf(w0, col[-(3 * 2 * DI)], s);
    if (l >= 2) s = fmaf(w1, col[-(2 * 2 * DI)], s);
    if (l >= 1) s = fmaf(w2, col[-(1 * 2 * DI)], s);
    s = fmaf(w3, col[0], s);
    g_xs[idx] = tf32_rn(s / (1.f + __expf(-s)));
}

// ---------------- selective scan + D skip + gating ----------------------------
#define SC_DPB 32
#define SC_CH  64
__global__ void __launch_bounds__(256) scan_kernel(
    const float* __restrict__ A_log, const float* __restrict__ Dp)
{
    __shared__ float s_d[SC_CH][SC_DPB];
    __shared__ float s_u[SC_CH][SC_DPB];
    __shared__ float s_B[SC_CH][16];
    __shared__ float s_C[SC_CH][16];
    __shared__ float s_y[SC_CH][SC_DPB];
    const int b   = blockIdx.y;
    const int d0  = blockIdx.x * SC_DPB;
    const int tid = threadIdx.x;
    const int dl  = tid >> 3;
    const int tq  = tid & 7;
    const int d   = d0 + dl;
    const int n0  = tq * 2;

    const float LOG2E = 1.4426950408889634f;
    float a20 = -expf(A_log[d * NS + n0 + 0]) * LOG2E;
    float a21 = -expf(A_log[d * NS + n0 + 1]) * LOG2E;
    float Dv  = Dp[d];
    float h0 = 0.f, h1 = 0.f;

    for (int l0 = 0; l0 < LL; l0 += SC_CH) {
        for (int i = tid; i < SC_CH * SC_DPB; i += 256) {
            int li = i >> 5, dd = i & 31;
            size_t gg = ((size_t)(b * LL + l0 + li)) * DI + d0 + dd;
            s_d[li][dd] = g_delta[gg];
            s_u[li][dd] = g_xs[gg];
        }
        for (int i = tid; i < SC_CH * 16; i += 256) {
            int li = i >> 4, nn = i & 15;
            const float* row = g_xdbl + ((size_t)(b * LL + l0 + li)) * 96;
            s_B[li][nn] = row[64 + nn];
            s_C[li][nn] = row[80 + nn];
        }
        __syncthreads();
        #pragma unroll 4
        for (int li = 0; li < SC_CH; ++li) {
            float dv = s_d[li][dl];
            float uv = s_u[li][dl];
            float du = dv * uv;
            float dA0 = ex2_approx(dv * a20);
            float dA1 = ex2_approx(dv * a21);
            h0 = fmaf(dA0, h0, du * s_B[li][n0 + 0]);
            h1 = fmaf(dA1, h1, du * s_B[li][n0 + 1]);
            float acc = fmaf(h0, s_C[li][n0 + 0], h1 * s_C[li][n0 + 1]);
            acc += __shfl_xor_sync(0xffffffffu, acc, 1);
            acc += __shfl_xor_sync(0xffffffffu, acc, 2);
            acc += __shfl_xor_sync(0xffffffffu, acc, 4);
            if (tq == 0) s_y[li][dl] = fmaf(uv, Dv, acc);
        }
        __syncthreads();
        for (int i = tid; i < SC_CH * SC_DPB; i += 256) {
            int li = i >> 5, dd = i & 31;
            size_t bl = (size_t)(b * LL + l0 + li);
            float r  = g_xr[bl * (2 * DI) + DI + d0 + dd];
            float sr = r / (1.f + __expf(-r));
            g_yg[bl * DI + d0 + dd] = tf32_rn(s_y[li][dd] * sr);
        }
    }
}

// ---------------- launch ------------------------------------------------------
extern "C" void kernel_launch(void* const* d_in, const int* in_sizes, int n_in,
                              void* d_out, int out_size)
{
    (void)in_sizes; (void)n_in; (void)out_size;
    const float* x      = (const float*)d_in[0];
    const float* W_in   = (const float*)d_in[1];
    const float* conv_w = (const float*)d_in[2];
    const float* conv_b = (const float*)d_in[3];
    const float* W_x    = (const float*)d_in[4];
    const float* W_dt   = (const float*)d_in[5];
    const float* b_dt   = (const float*)d_in[6];
    const float* A_log  = (const float*)d_in[7];
    const float* Dp     = (const float*)d_in[8];
    const float* W_out  = (const float*)d_in[9];
    float* out = (float*)d_out;

    float *p_xr, *p_xs, *p_xdbl, *p_delta, *p_yg;
    float *p_xa, *p_wi, *p_wx, *p_wdt, *p_wo;
    cudaGetSymbolAddress((void**)&p_xr,    g_xr);
    cudaGetSymbolAddress((void**)&p_xs,    g_xs);
    cudaGetSymbolAddress((void**)&p_xdbl,  g_xdbl);
    cudaGetSymbolAddress((void**)&p_delta, g_delta);
    cudaGetSymbolAddress((void**)&p_yg,    g_yg);
    cudaGetSymbolAddress((void**)&p_xa,    g_xa);
    cudaGetSymbolAddress((void**)&p_wi,    g_wi);
    cudaGetSymbolAddress((void**)&p_wx,    g_wx);
    cudaGetSymbolAddress((void**)&p_wdt,   g_wdt);
    cudaGetSymbolAddress((void**)&p_wo,    g_wo);

    const int SMEM = 4 * 128 * 36 * 4 * 2;   // 147456 bytes
    cudaFuncSetAttribute(gemm_mma<0, 0>,  cudaFuncAttributeMaxDynamicSharedMemorySize, SMEM);
    cudaFuncSetAttribute(gemm_mma<1, 0>,  cudaFuncAttributeMaxDynamicSharedMemorySize, SMEM);
    cudaFuncSetAttribute(gemm_mma<3, 96>, cudaFuncAttributeMaxDynamicSharedMemorySize, SMEM);

    // zero the split-K accumulator
    cudaMemsetAsync(p_xdbl, 0, (size_t)NT * 96 * sizeof(float));

    // TF32-RN rounding of GEMM operands (exact R3 numerics)
    round_tf32_kernel<<<4096, 256>>>(x,     p_xa,  NT * DM / 4);
    round_tf32_kernel<<<4096, 256>>>(W_in,  p_wi,  2 * DI * DM / 4);
    round_tf32_kernel<<<192,  256>>>(W_x,   p_wx,  96 * DI / 4);
    round_tf32_kernel<<<128,  256>>>(W_dt,  p_wdt, DI * DTR / 4);
    round_tf32_kernel<<<2048, 256>>>(W_out, p_wo,  DM * DI / 4);

    // 1) xr = x @ W_in^T   [4096,1024]x[4096,1024]^T -> [4096,4096]
    gemm_mma<0, 0><<<dim3(32, 32, 1), 256, SMEM>>>(
        p_xa, p_wi, nullptr, p_xr, DM, DM, DM, 2 * DI);

    // 2) xs = tf32(silu(causal dwconv(xr[:, :DI])))
    conv_silu_kernel<<<(NT * DI) / 256, 256>>>(conv_w, conv_b);

    // 3) x_dbl = xs @ W_x^T  split-K=8, atomicAdd  -> [4096,96]
    gemm_mma<3, 96><<<dim3(1, 32, 8), 256, SMEM>>>(
        p_xs, p_wx, nullptr, p_xdbl, DI / 8, DI, DI, 96);

    // round x_dbl to tf32 (feeds dt GEMM; scan reads rounded B/C)
    round_tf32_kernel<<<384, 256>>>(p_xdbl, p_xdbl, NT * 96 / 4);

    // 4) delta = softplus(x_dbl[:, :64] @ W_dt^T + b_dt)   K=64
    gemm_mma<1, 0><<<dim3(16, 32, 1), 256, SMEM>>>(
        p_xdbl, p_wdt, b_dt, p_delta, DTR, 96, DTR, DI);

    // 5) selective scan (+D skip, *silu(res)) -> g_yg
    scan_kernel<<<dim3(DI / SC_DPB, BB), 256>>>(A_log, Dp);

    // 6) out = yg @ W_out^T  [4096,2048]x[1024,2048]^T -> [4096,1024]
    gemm_mma<0, 0><<<dim3(8, 32, 1), 256, SMEM>>>(
        p_yg, p_wo, nullptr, out, DI, DI, DI, DM);
}

// round 11
// speedup vs baseline: 1.0090x; 1.0090x over previous
#include <cuda_runtime.h>
#include <math.h>
#include <stdint.h>

#define DM   1024
#define DI   2048
#define DTR  64
#define NS   16
#define BB   4
#define LL   1024
#define NT   (BB*LL)

// ---------------- scratch ----------------------------------------------------
__device__ __align__(16) float g_xr  [(size_t)NT * 2 * DI];
__device__ __align__(16) float g_xs  [(size_t)NT * DI];
__device__ __align__(16) float g_xdbl[(size_t)NT * 96];
__device__ __align__(16) float g_delta[(size_t)NT * DI];
__device__ __align__(16) float g_yg  [(size_t)NT * DI];
__device__ __align__(16) float g_xa  [(size_t)NT * DM];
__device__ __align__(16) float g_wi  [(size_t)2 * DI * DM];
__device__ __align__(16) float g_wx  [(size_t)96 * DI];
__device__ __align__(16) float g_wdt [(size_t)DI * DTR];
__device__ __align__(16) float g_wo  [(size_t)DM * DI];

// ---------------- helpers -----------------------------------------------------
__device__ __forceinline__ float ex2_approx(float x) {
    float y; asm("ex2.approx.f32 %0, %1;" : "=f"(y) : "f"(x)); return y;
}
__device__ __forceinline__ float tf32_rn(float x) {
    float r; asm("cvt.rna.tf32.f32 %0, %1;" : "=f"(r) : "f"(x)); return r;
}
__device__ __forceinline__ void mma_tf32(float* c, const uint32_t* a, const uint32_t* b) {
    asm volatile(
        "mma.sync.aligned.m16n8k8.row.col.f32.tf32.tf32.f32 "
        "{%0,%1,%2,%3}, {%4,%5,%6,%7}, {%8,%9}, {%0,%1,%2,%3};"
        : "+f"(c[0]), "+f"(c[1]), "+f"(c[2]), "+f"(c[3])
        : "r"(a[0]), "r"(a[1]), "r"(a[2]), "r"(a[3]), "r"(b[0]), "r"(b[1]));
}

// ---------------- TF32 mma.sync GEMM:  C[M,N] = A[M,K] * B[N,K]^T -------------
// BM=BN=128, BK=32, 4-stage cp.async, 256 thr, warp tile 32x64.
// EPI: 0 none, 1 softplus(x+bias[n]), 3 atomicAdd (split-K; NGUARD=valid N)
template<int EPI, int NGUARD>
__global__ void __launch_bounds__(256, 1) gemm_mma(
    const float* __restrict__ A, const float* __restrict__ B,
    const float* __restrict__ bias, float* __restrict__ C,
    int K, int lda, int ldb, int ldc)
{
    constexpr int ST = 4;
    constexpr int P  = 36;             // smem row pitch (floats)
    constexpr int TILE = 128 * P;      // floats per stage per operand
    extern __shared__ float sm[];
    float* As = sm;
    float* Bs = sm + ST * TILE;

    const int tid  = threadIdx.x;
    const int wid  = tid >> 5, lane = tid & 31;
    const int g    = lane >> 2, q = lane & 3;
    const int bm   = blockIdx.y * 128;
    const int bn   = blockIdx.x * 128;
    const int T    = K >> 5;
    const int mbase = (wid & 3) * 32;
    const int nbase = (wid >> 2) * 64;

    const float* Ab = A + (size_t)bm * lda + (size_t)blockIdx.z * K;
    const float* Bb = B + (size_t)bn * ldb + (size_t)blockIdx.z * K;

    auto load_tile = [&](int st, int t) {
        float* as = As + st * TILE;
        float* bs = Bs + st * TILE;
        #pragma unroll
        for (int i = 0; i < 4; ++i) {
            int c = tid + i * 256;
            int r = c >> 3, col = (c & 7) * 4;
            const float* src = Ab + (size_t)r * lda + t * 32 + col;
            uint32_t dst = (uint32_t)__cvta_generic_to_shared(as + r * P + col);
            asm volatile("cp.async.cg.shared.global [%0], [%1], 16;"
                         :: "r"(dst), "l"(src));
        }
        #pragma unroll
        for (int i = 0; i < 4; ++i) {
            int c = tid + i * 256;
            int r = c >> 3, col = (c & 7) * 4;
            uint32_t dst = (uint32_t)__cvta_generic_to_shared(bs + r * P + col);
            if (NGUARD && (bn + r) >= NGUARD) {
                asm volatile("cp.async.cg.shared.global [%0], [%1], 16, 0;"
                             :: "r"(dst), "l"(Bb));
            } else {
                const float* src = Bb + (size_t)r * ldb + t * 32 + col;
                asm volatile("cp.async.cg.shared.global [%0], [%1], 16;"
                             :: "r"(dst), "l"(src));
            }
        }
    };

    float c[2][8][4];
    #pragma unroll
    for (int t = 0; t < 2; ++t)
        #pragma unroll
        for (int j = 0; j < 8; ++j)
            #pragma unroll
            for (int i = 0; i < 4; ++i) c[t][j][i] = 0.f;

    #pragma unroll
    for (int s = 0; s < ST - 1; ++s) {
        if (s < T) load_tile(s, s);
        asm volatile("cp.async.commit_group;");
    }

    for (int t = 0; t < T; ++t) {
        asm volatile("cp.async.wait_group 2;");
        __syncthreads();
        const int st = t & 3;
        const float* as0 = As + st * TILE;
        const float* bs0 = Bs + st * TILE;
        #pragma unroll
        for (int k8 = 0; k8 < 4; ++k8) {
            const int k0 = k8 * 8 + q;
            uint32_t a[2][4], b[8][2];
            #pragma unroll
            for (int tt = 0; tt < 2; ++tt) {
                const float* ap = as0 + (mbase + tt * 16 + g) * P + k0;
                a[tt][0] = __float_as_uint(ap[0]);
                a[tt][1] = __float_as_uint(ap[8 * P]);
                a[tt][2] = __float_as_uint(ap[4]);
                a[tt][3] = __float_as_uint(ap[8 * P + 4]);
            }
            #pragma unroll
            for (int j = 0; j < 8; ++j) {
                const float* bp = bs0 + (nbase + j * 8 + g) * P + k0;
                b[j][0] = __float_as_uint(bp[0]);
                b[j][1] = __float_as_uint(bp[4]);
            }
            #pragma unroll
            for (int tt = 0; tt < 2; ++tt)
                #pragma unroll
                for (int j = 0; j < 8; ++j)
                    mma_tf32(c[tt][j], a[tt], b[j]);
        }
        const int kt = t + ST - 1;
        if (kt < T) load_tile(kt & 3, kt);
        asm volatile("cp.async.commit_group;");
    }

    // epilogue
    #pragma unroll
    for (int tt = 0; tt < 2; ++tt) {
        const int r0 = bm + mbase + tt * 16 + g;
        #pragma unroll
        for (int j = 0; j < 8; ++j) {
            const int col = bn + nbase + j * 8 + q * 2;
            float v0 = c[tt][j][0], v1 = c[tt][j][1];
            float v2 = c[tt][j][2], v3 = c[tt][j][3];
            if (EPI == 1) {
                float b0 = bias[col], b1 = bias[col + 1];
                v0 += b0; v1 += b1; v2 += b0; v3 += b1;
                v0 = (v0 > 20.f) ? v0 : log1pf(__expf(v0));
                v1 = (v1 > 20.f) ? v1 : log1pf(__expf(v1));
                v2 = (v2 > 20.f) ? v2 : log1pf(__expf(v2));
                v3 = (v3 > 20.f) ? v3 : log1pf(__expf(v3));
            }
            if (EPI == 3) {
                if (!NGUARD || col < NGUARD) {
                    atomicAdd(&C[(size_t)r0 * ldc + col], v0);
                    atomicAdd(&C[(size_t)r0 * ldc + col + 1], v1);
                    atomicAdd(&C[(size_t)(r0 + 8) * ldc + col], v2);
                    atomicAdd(&C[(size_t)(r0 + 8) * ldc + col + 1], v3);
                }
            } else {
                float2 p0 = make_float2(v0, v1);
                float2 p1 = make_float2(v2, v3);
                *(float2*)&C[(size_t)r0 * ldc + col] = p0;
                *(float2*)&C[(size_t)(r0 + 8) * ldc + col] = p1;
            }
        }
    }
}

// ---------------- tf32 rounding copy ------------------------------------------
__global__ void round_tf32_kernel(const float* __restrict__ src,
                                  float* __restrict__ dst, int n4)
{
    int i = blockIdx.x * blockDim.x + threadIdx.x;
    if (i < n4) {
        float4 v = ((const float4*)src)[i];
        v.x = tf32_rn(v.x); v.y = tf32_rn(v.y);
        v.z = tf32_rn(v.z); v.w = tf32_rn(v.w);
        ((float4*)dst)[i] = v;
    }
}

// ---------------- causal depthwise conv1d (width 4) + SiLU --------------------
__global__ void conv_silu_kernel(const float* __restrict__ conv_w,
                                 const float* __restrict__ conv_b)
{
    int idx = blockIdx.x * blockDim.x + threadIdx.x;
    int d  = idx & (DI - 1);
    int bl = idx >> 11;
    int l  = bl & (LL - 1);
    float w0 = conv_w[d * 4 + 0], w1 = conv_w[d * 4 + 1];
    float w2 = conv_w[d * 4 + 2], w3 = conv_w[d * 4 + 3];
    const float* col = g_xr + (size_t)bl * (2 * DI) + d;
    float s = conv_b[d];
    if (l >= 3) s = fmaf(w0, col[-(3 * 2 * DI)], s);
    if (l >= 2) s = fmaf(w1, col[-(2 * 2 * DI)], s);
    if (l >= 1) s = fmaf(w2, col[-(1 * 2 * DI)], s);
    s = fmaf(w3, col[0], s);
    g_xs[idx] = tf32_rn(s / (1.f + __expf(-s)));
}

// ---------------- selective scan + D skip + gating ----------------------------
#define SC_DPB 32
#define SC_CH  64
__global__ void __launch_bounds__(256) scan_kernel(
    const float* __restrict__ A_log, const float* __restrict__ Dp)
{
    __shared__ float s_d[SC_CH][SC_DPB];
    __shared__ float s_u[SC_CH][SC_DPB];
    __shared__ float s_B[SC_CH][16];
    __shared__ float s_C[SC_CH][16];
    __shared__ float s_y[SC_CH][SC_DPB];
    const int b   = blockIdx.y;
    const int d0  = blockIdx.x * SC_DPB;
    const int tid = threadIdx.x;
    const int dl  = tid >> 3;
    const int tq  = tid & 7;
    const int d   = d0 + dl;
    const int n0  = tq * 2;

    const float LOG2E = 1.4426950408889634f;
    float a20 = -expf(A_log[d * NS + n0 + 0]) * LOG2E;
    float a21 = -expf(A_log[d * NS + n0 + 1]) * LOG2E;
    float Dv  = Dp[d];
    float h0 = 0.f, h1 = 0.f;

    for (int l0 = 0; l0 < LL; l0 += SC_CH) {
        for (int i = tid; i < SC_CH * SC_DPB; i += 256) {
            int li = i >> 5, dd = i & 31;
            size_t gg = ((size_t)(b * LL + l0 + li)) * DI + d0 + dd;
            s_d[li][dd] = g_delta[gg];
            s_u[li][dd] = g_xs[gg];
        }
        for (int i = tid; i < SC_CH * 16; i += 256) {
            int li = i >> 4, nn = i & 15;
            const float* row = g_xdbl + ((size_t)(b * LL + l0 + li)) * 96;
            s_B[li][nn] = row[64 + nn];
            s_C[li][nn] = row[80 + nn];
        }
        __syncthreads();
        #pragma unroll 4
        for (int li = 0; li < SC_CH; ++li) {
            float dv = s_d[li][dl];
            float uv = s_u[li][dl];
            float du = dv * uv;
            float dA0 = ex2_approx(dv * a20);
            float dA1 = ex2_approx(dv * a21);
            h0 = fmaf(dA0, h0, du * s_B[li][n0 + 0]);
            h1 = fmaf(dA1, h1, du * s_B[li][n0 + 1]);
            float acc = fmaf(h0, s_C[li][n0 + 0], h1 * s_C[li][n0 + 1]);
            acc += __shfl_xor_sync(0xffffffffu, acc, 1);
            acc += __shfl_xor_sync(0xffffffffu, acc, 2);
            acc += __shfl_xor_sync(0xffffffffu, acc, 4);
            if (tq == 0) s_y[li][dl] = fmaf(uv, Dv, acc);
        }
        __syncthreads();
        for (int i = tid; i < SC_CH * SC_DPB; i += 256) {
            int li = i >> 5, dd = i & 31;
            size_t bl = (size_t)(b * LL + l0 + li);
            float r  = g_xr[bl * (2 * DI) + DI + d0 + dd];
            float sr = r / (1.f + __expf(-r));
            g_yg[bl * DI + d0 + dd] = tf32_rn(s_y[li][dd] * sr);
        }
    }
}

// ---------------- launch ------------------------------------------------------
extern "C" void kernel_launch(void* const* d_in, const int* in_sizes, int n_in,
                              void* d_out, int out_size)
{
    (void)in_sizes; (void)n_in; (void)out_size;
    const float* x      = (const float*)d_in[0];
    const float* W_in   = (const float*)d_in[1];
    const float* conv_w = (const float*)d_in[2];
    const float* conv_b = (const float*)d_in[3];
    const float* W_x    = (const float*)d_in[4];
    const float* W_dt   = (const float*)d_in[5];
    const float* b_dt   = (const float*)d_in[6];
    const float* A_log  = (const float*)d_in[7];
    const float* Dp     = (const float*)d_in[8];
    const float* W_out  = (const float*)d_in[9];
    float* out = (float*)d_out;

    float *p_xr, *p_xs, *p_xdbl, *p_delta, *p_yg;
    float *p_xa, *p_wi, *p_wx, *p_wdt, *p_wo;
    cudaGetSymbolAddress((void**)&p_xr,    g_xr);
    cudaGetSymbolAddress((void**)&p_xs,    g_xs);
    cudaGetSymbolAddress((void**)&p_xdbl,  g_xdbl);
    cudaGetSymbolAddress((void**)&p_delta, g_delta);
    cudaGetSymbolAddress((void**)&p_yg,    g_yg);
    cudaGetSymbolAddress((void**)&p_xa,    g_xa);
    cudaGetSymbolAddress((void**)&p_wi,    g_wi);
    cudaGetSymbolAddress((void**)&p_wx,    g_wx);
    cudaGetSymbolAddress((void**)&p_wdt,   g_wdt);
    cudaGetSymbolAddress((void**)&p_wo,    g_wo);

    const int SMEM = 4 * 128 * 36 * 4 * 2;   // 147456 bytes
    cudaFuncSetAttribute(gemm_mma<0, 0>,  cudaFuncAttributeMaxDynamicSharedMemorySize, SMEM);
    cudaFuncSetAttribute(gemm_mma<1, 0>,  cudaFuncAttributeMaxDynamicSharedMemorySize, SMEM);
    cudaFuncSetAttribute(gemm_mma<3, 96>, cudaFuncAttributeMaxDynamicSharedMemorySize, SMEM);

    // zero the split-K accumulator
    cudaMemsetAsync(p_xdbl, 0, (size_t)NT * 96 * sizeof(float));

    // TF32-RN rounding of GEMM operands
    round_tf32_kernel<<<4096, 256>>>(x,     p_xa,  NT * DM / 4);
    round_tf32_kernel<<<4096, 256>>>(W_in,  p_wi,  2 * DI * DM / 4);
    round_tf32_kernel<<<192,  256>>>(W_x,   p_wx,  96 * DI / 4);
    round_tf32_kernel<<<128,  256>>>(W_dt,  p_wdt, DI * DTR / 4);
    round_tf32_kernel<<<2048, 256>>>(W_out, p_wo,  DM * DI / 4);

    // 1) xr = x @ W_in^T   [4096,1024]x[4096,1024]^T -> [4096,4096]
    gemm_mma<0, 0><<<dim3(32, 32, 1), 256, SMEM>>>(
        p_xa, p_wi, nullptr, p_xr, DM, DM, DM, 2 * DI);

    // 2) xs = tf32(silu(causal dwconv(xr[:, :DI])))
    conv_silu_kernel<<<(NT * DI) / 256, 256>>>(conv_w, conv_b);

    // 3) x_dbl = xs @ W_x^T  split-K=8, atomicAdd  -> [4096,96]
    gemm_mma<3, 96><<<dim3(1, 32, 8), 256, SMEM>>>(
        p_xs, p_wx, nullptr, p_xdbl, DI / 8, DI, DI, 96);

    // round x_dbl to tf32 (feeds dt GEMM; scan reads rounded B/C)
    round_tf32_kernel<<<384, 256>>>(p_xdbl, p_xdbl, NT * 96 / 4);

    // 4) delta = softplus(x_dbl[:, :64] @ W_dt^T + b_dt)   K=64
    gemm_mma<1, 0><<<dim3(16, 32, 1), 256, SMEM>>>(
        p_xdbl, p_wdt, b_dt, p_delta, DTR, 96, DTR, DI);

    // 5) selective scan (+D skip, *silu(res)) -> g_yg
    scan_kernel<<<dim3(DI / SC_DPB, BB), 256>>>(A_log, Dp);

    // 6) out = yg @ W_out^T  [4096,2048]x[1024,2048]^T -> [4096,1024]
    gemm_mma<0, 0><<<dim3(8, 32, 1), 256, SMEM>>>(
        p_yg, p_wo, nullptr, out, DI, DI, DI, DM);
}

// round 12
// speedup vs baseline: 1.0886x; 1.0789x over previous
#include <cuda_runtime.h>
#include <math.h>
#include <stdint.h>

#define DM   1024
#define DI   2048
#define DTR  64
#define NS   16
#define BB   4
#define LL   1024
#define NT   (BB*LL)

// ---------------- scratch ----------------------------------------------------
__device__ __align__(16) float g_xr  [(size_t)NT * 2 * DI];
__device__ __align__(16) float g_xs  [(size_t)NT * DI];
__device__ __align__(16) float g_xdbl[(size_t)NT * 96];
__device__ __align__(16) float g_delta[(size_t)NT * DI];
__device__ __align__(16) float g_yg  [(size_t)NT * DI];
__device__ __align__(16) float g_wi  [(size_t)2 * DI * DM];
__device__ __align__(16) float g_wx  [(size_t)96 * DI];
__device__ __align__(16) float g_wdt [(size_t)DI * DTR];
__device__ __align__(16) float g_wo  [(size_t)DM * DI];

// ---------------- helpers -----------------------------------------------------
__device__ __forceinline__ float ex2_approx(float x) {
    float y; asm("ex2.approx.f32 %0, %1;" : "=f"(y) : "f"(x)); return y;
}
__device__ __forceinline__ float tf32_rn(float x) {
    float r; asm("cvt.rna.tf32.f32 %0, %1;" : "=f"(r) : "f"(x)); return r;
}
__device__ __forceinline__ void mma_tf32(float* c, const uint32_t* a, const uint32_t* b) {
    asm volatile(
        "mma.sync.aligned.m16n8k8.row.col.f32.tf32.tf32.f32 "
        "{%0,%1,%2,%3}, {%4,%5,%6,%7}, {%8,%9}, {%0,%1,%2,%3};"
        : "+f"(c[0]), "+f"(c[1]), "+f"(c[2]), "+f"(c[3])
        : "r"(a[0]), "r"(a[1]), "r"(a[2]), "r"(a[3]), "r"(b[0]), "r"(b[1]));
}

// ---------------- TF32 mma.sync GEMM:  C[M,N] = A[M,K] * B[N,K]^T -------------
// BM=BN=128, BK=32, 3-stage cp.async, 128 threads: 4 warps of 64x64 (2M x 2N).
// smem 110.6KB -> 2 CTAs/SM. (Best measured config under current environment.)
// RNDA=1: round A fragments to tf32 in-register (A may be raw fp32).
// B (weights) must be pre-rounded.
// EPI: 0 none, 1 softplus(x+bias[n]), 3 atomicAdd (split-K; NGUARD=valid N)
template<int EPI, int NGUARD, int RNDA>
__global__ void __launch_bounds__(128, 2) gemm_mma(
    const float* __restrict__ A, const float* __restrict__ B,
    const float* __restrict__ bias, float* __restrict__ C,
    int K, int lda, int ldb, int ldc)
{
    constexpr int ST = 3;
    constexpr int P  = 36;                 // smem row pitch (floats)
    constexpr int ATILE = 128 * P;
    constexpr int BTILE = 128 * P;
    extern __shared__ float sm[];
    float* As = sm;
    float* Bs = sm + ST * ATILE;

    const int tid  = threadIdx.x;
    const int wid  = tid >> 5, lane = tid & 31;
    const int g    = lane >> 2, q = lane & 3;
    const int bm   = blockIdx.y * 128;
    const int bn   = blockIdx.x * 128;
    const int T    = K >> 5;
    const int mbase = (wid & 1) * 64;
    const int nbase = (wid >> 1) * 64;

    const float* Ab = A + (size_t)bm * lda + (size_t)blockIdx.z * K;
    const float* Bb = B + (size_t)bn * ldb + (size_t)blockIdx.z * K;

    auto load_tile = [&](int st, int t) {
        float* as = As + st * ATILE;
        float* bs = Bs + st * BTILE;
        #pragma unroll
        for (int i = 0; i < 8; ++i) {
            int c = tid + i * 128;
            int r = c >> 3, col = (c & 7) * 4;
            const float* src = Ab + (size_t)r * lda + t * 32 + col;
            uint32_t dst = (uint32_t)__cvta_generic_to_shared(as + r * P + col);
            asm volatile("cp.async.cg.shared.global [%0], [%1], 16;"
                         :: "r"(dst), "l"(src));
        }
        #pragma unroll
        for (int i = 0; i < 8; ++i) {
            int c = tid + i * 128;
            int r = c >> 3, col = (c & 7) * 4;
            uint32_t dst = (uint32_t)__cvta_generic_to_shared(bs + r * P + col);
            if (NGUARD && (bn + r) >= NGUARD) {
                asm volatile("cp.async.cg.shared.global [%0], [%1], 16, 0;"
                             :: "r"(dst), "l"(Bb));
            } else {
                const float* src = Bb + (size_t)r * ldb + t * 32 + col;
                asm volatile("cp.async.cg.shared.global [%0], [%1], 16;"
                             :: "r"(dst), "l"(src));
            }
        }
    };

    float c[4][8][4];
    #pragma unroll
    for (int t = 0; t < 4; ++t)
        #pragma unroll
        for (int j = 0; j < 8; ++j)
            #pragma unroll
            for (int i = 0; i < 4; ++i) c[t][j][i] = 0.f;

    #pragma unroll
    for (int s = 0; s < ST - 1; ++s) {
        if (s < T) load_tile(s, s);
        asm volatile("cp.async.commit_group;");
    }

    int cs = 0, ls = 2;
    for (int t = 0; t < T; ++t) {
        asm volatile("cp.async.wait_group 1;");
        __syncthreads();
        const float* as0 = As + cs * ATILE;
        const float* bs0 = Bs + cs * BTILE;
        #pragma unroll
        for (int k8 = 0; k8 < 4; ++k8) {
            const int k0 = k8 * 8 + q;
            uint32_t b[8][2];
            #pragma unroll
            for (int j = 0; j < 8; ++j) {
                const float* bp = bs0 + (nbase + j * 8 + g) * P + k0;
                b[j][0] = __float_as_uint(bp[0]);
                b[j][1] = __float_as_uint(bp[4]);
            }
            #pragma unroll
            for (int tt = 0; tt < 4; ++tt) {
                uint32_t a[4];
                const float* ap = as0 + (mbase + tt * 16 + g) * P + k0;
                if (RNDA) {
                    a[0] = __float_as_uint(tf32_rn(ap[0]));
                    a[1] = __float_as_uint(tf32_rn(ap[8 * P]));
                    a[2] = __float_as_uint(tf32_rn(ap[4]));
                    a[3] = __float_as_uint(tf32_rn(ap[8 * P + 4]));
                } else {
                    a[0] = __float_as_uint(ap[0]);
                    a[1] = __float_as_uint(ap[8 * P]);
                    a[2] = __float_as_uint(ap[4]);
                    a[3] = __float_as_uint(ap[8 * P + 4]);
                }
                #pragma unroll
                for (int j = 0; j < 8; ++j)
                    mma_tf32(c[tt][j], a, b[j]);
            }
        }
        const int kt = t + ST - 1;
        if (kt < T) load_tile(ls, kt);
        asm volatile("cp.async.commit_group;");
        cs = (cs == 2) ? 0 : cs + 1;
        ls = (ls == 2) ? 0 : ls + 1;
    }

    // epilogue
    #pragma unroll
    for (int tt = 0; tt < 4; ++tt) {
        const int r0 = bm + mbase + tt * 16 + g;
        #pragma unroll
        for (int j = 0; j < 8; ++j) {
            const int col = bn + nbase + j * 8 + q * 2;
            float v0 = c[tt][j][0], v1 = c[tt][j][1];
            float v2 = c[tt][j][2], v3 = c[tt][j][3];
            if (EPI == 1) {
                float b0 = bias[col], b1 = bias[col + 1];
                v0 += b0; v1 += b1; v2 += b0; v3 += b1;
                v0 = (v0 > 20.f) ? v0 : log1pf(__expf(v0));
                v1 = (v1 > 20.f) ? v1 : log1pf(__expf(v1));
                v2 = (v2 > 20.f) ? v2 : log1pf(__expf(v2));
                v3 = (v3 > 20.f) ? v3 : log1pf(__expf(v3));
            }
            if (EPI == 3) {
                if (!NGUARD || col < NGUARD) {
                    atomicAdd(&C[(size_t)r0 * ldc + col], v0);
                    atomicAdd(&C[(size_t)r0 * ldc + col + 1], v1);
                    atomicAdd(&C[(size_t)(r0 + 8) * ldc + col], v2);
                    atomicAdd(&C[(size_t)(r0 + 8) * ldc + col + 1], v3);
                }
            } else {
                float2 p0 = make_float2(v0, v1);
                float2 p1 = make_float2(v2, v3);
                *(float2*)&C[(size_t)r0 * ldc + col] = p0;
                *(float2*)&C[(size_t)(r0 + 8) * ldc + col] = p1;
            }
        }
    }
}

// ---------------- merged weight rounding (all 4 weights, one launch) ----------
#define WI4  (2 * DI * DM / 4)          // 1048576
#define WX4  (96 * DI / 4)              // 49152
#define WDT4 (DI * DTR / 4)             // 32768
#define WO4  (DM * DI / 4)              // 524288
__global__ void round_weights_kernel(
    const float* __restrict__ W_in, const float* __restrict__ W_x,
    const float* __restrict__ W_dt, const float* __restrict__ W_out,
    float* __restrict__ wi, float* __restrict__ wx,
    float* __restrict__ wdt, float* __restrict__ wo)
{
    int i = blockIdx.x * blockDim.x + threadIdx.x;
    const float4* src; float4* dst; int idx;
    if (i < WI4)                          { src = (const float4*)W_in;  dst = (float4*)wi;  idx = i; }
    else if (i < WI4 + WO4)               { src = (const float4*)W_out; dst = (float4*)wo;  idx = i - WI4; }
    else if (i < WI4 + WO4 + WX4)         { src = (const float4*)W_x;   dst = (float4*)wx;  idx = i - WI4 - WO4; }
    else if (i < WI4 + WO4 + WX4 + WDT4)  { src = (const float4*)W_dt;  dst = (float4*)wdt; idx = i - WI4 - WO4 - WX4; }
    else return;
    float4 v = src[idx];
    v.x = tf32_rn(v.x); v.y = tf32_rn(v.y);
    v.z = tf32_rn(v.z); v.w = tf32_rn(v.w);
    dst[idx] = v;
}

// ---------------- causal depthwise conv1d (width 4) + SiLU (+tf32) ------------
__global__ void conv_silu_kernel(const float* __restrict__ conv_w,
                                 const float* __restrict__ conv_b)
{
    int idx = blockIdx.x * blockDim.x + threadIdx.x;
    int d  = idx & (DI - 1);
    int bl = idx >> 11;
    int l  = bl & (LL - 1);
    float w0 = conv_w[d * 4 + 0], w1 = conv_w[d * 4 + 1];
    float w2 = conv_w[d * 4 + 2], w3 = conv_w[d * 4 + 3];
    const float* col = g_xr + (size_t)bl * (2 * DI) + d;
    float s = conv_b[d];
    if (l >= 3) s = fmaf(w0, col[-(3 * 2 * DI)], s);
    if (l >= 2) s = fmaf(w1, col[-(2 * 2 * DI)], s);
    if (l >= 1) s = fmaf(w2, col[-(1 * 2 * DI)], s);
    s = fmaf(w3, col[0], s);
    g_xs[idx] = tf32_rn(s / (1.f + __expf(-s)));
}

// ---------------- selective scan + D skip + gating ----------------------------
#define SC_DPB 32
#define SC_CH  64
__global__ void __launch_bounds__(256) scan_kernel(
    const float* __restrict__ A_log, const float* __restrict__ Dp)
{
    __shared__ float s_d[SC_CH][SC_DPB];
    __shared__ float s_u[SC_CH][SC_DPB];
    __shared__ float s_B[SC_CH][16];
    __shared__ float s_C[SC_CH][16];
    __shared__ float s_y[SC_CH][SC_DPB];
    const int b   = blockIdx.y;
    const int d0  = blockIdx.x * SC_DPB;
    const int tid = threadIdx.x;
    const int dl  = tid >> 3;
    const int tq  = tid & 7;
    const int d   = d0 + dl;
    const int n0  = tq * 2;

    const float LOG2E = 1.4426950408889634f;
    float a20 = -expf(A_log[d * NS + n0 + 0]) * LOG2E;
    float a21 = -expf(A_log[d * NS + n0 + 1]) * LOG2E;
    float Dv  = Dp[d];
    float h0 = 0.f, h1 = 0.f;

    for (int l0 = 0; l0 < LL; l0 += SC_CH) {
        for (int i = tid; i < SC_CH * SC_DPB; i += 256) {
            int li = i >> 5, dd = i & 31;
            size_t gg = ((size_t)(b * LL + l0 + li)) * DI + d0 + dd;
            s_d[li][dd] = g_delta[gg];
            s_u[li][dd] = g_xs[gg];
        }
        for (int i = tid; i < SC_CH * 16; i += 256) {
            int li = i >> 4, nn = i & 15;
            const float* row = g_xdbl + ((size_t)(b * LL + l0 + li)) * 96;
            s_B[li][nn] = row[64 + nn];
            s_C[li][nn] = row[80 + nn];
        }
        __syncthreads();
        #pragma unroll 4
        for (int li = 0; li < SC_CH; ++li) {
            float dv = s_d[li][dl];
            float uv = s_u[li][dl];
            float du = dv * uv;
            float dA0 = ex2_approx(dv * a20);
            float dA1 = ex2_approx(dv * a21);
            h0 = fmaf(dA0, h0, du * s_B[li][n0 + 0]);
            h1 = fmaf(dA1, h1, du * s_B[li][n0 + 1]);
            float acc = fmaf(h0, s_C[li][n0 + 0], h1 * s_C[li][n0 + 1]);
            acc += __shfl_xor_sync(0xffffffffu, acc, 1);
            acc += __shfl_xor_sync(0xffffffffu, acc, 2);
            acc += __shfl_xor_sync(0xffffffffu, acc, 4);
            if (tq == 0) s_y[li][dl] = fmaf(uv, Dv, acc);
        }
        __syncthreads();
        for (int i = tid; i < SC_CH * SC_DPB; i += 256) {
            int li = i >> 5, dd = i & 31;
            size_t bl = (size_t)(b * LL + l0 + li);
            float r  = g_xr[bl * (2 * DI) + DI + d0 + dd];
            float sr = r / (1.f + __expf(-r));
            g_yg[bl * DI + d0 + dd] = tf32_rn(s_y[li][dd] * sr);
        }
    }
}

// ---------------- launch ------------------------------------------------------
extern "C" void kernel_launch(void* const* d_in, const int* in_sizes, int n_in,
                              void* d_out, int out_size)
{
    (void)in_sizes; (void)n_in; (void)out_size;
    const float* x      = (const float*)d_in[0];
    const float* W_in   = (const float*)d_in[1];
    const float* conv_w = (const float*)d_in[2];
    const float* conv_b = (const float*)d_in[3];
    const float* W_x    = (const float*)d_in[4];
    const float* W_dt   = (const float*)d_in[5];
    const float* b_dt   = (const float*)d_in[6];
    const float* A_log  = (const float*)d_in[7];
    const float* Dp     = (const float*)d_in[8];
    const float* W_out  = (const float*)d_in[9];
    float* out = (float*)d_out;

    float *p_xr, *p_xs, *p_xdbl, *p_delta, *p_yg;
    float *p_wi, *p_wx, *p_wdt, *p_wo;
    cudaGetSymbolAddress((void**)&p_xr,    g_xr);
    cudaGetSymbolAddress((void**)&p_xs,    g_xs);
    cudaGetSymbolAddress((void**)&p_xdbl,  g_xdbl);
    cudaGetSymbolAddress((void**)&p_delta, g_delta);
    cudaGetSymbolAddress((void**)&p_yg,    g_yg);
    cudaGetSymbolAddress((void**)&p_wi,    g_wi);
    cudaGetSymbolAddress((void**)&p_wx,    g_wx);
    cudaGetSymbolAddress((void**)&p_wdt,   g_wdt);
    cudaGetSymbolAddress((void**)&p_wo,    g_wo);

    const int SMEM = 3 * (128 + 128) * 36 * 4;   // 110592 bytes -> 2 CTAs/SM
    cudaFuncSetAttribute(gemm_mma<0, 0, 1>,  cudaFuncAttributeMaxDynamicSharedMemorySize, SMEM);
    cudaFuncSetAttribute(gemm_mma<0, 0, 0>,  cudaFuncAttributeMaxDynamicSharedMemorySize, SMEM);
    cudaFuncSetAttribute(gemm_mma<1, 0, 1>,  cudaFuncAttributeMaxDynamicSharedMemorySize, SMEM);
    cudaFuncSetAttribute(gemm_mma<3, 96, 0>, cudaFuncAttributeMaxDynamicSharedMemorySize, SMEM);

    // zero the split-K accumulator
    cudaMemsetAsync(p_xdbl, 0, (size_t)NT * 96 * sizeof(float));

    // one merged TF32-RN weight rounding launch
    const int TOT4 = WI4 + WO4 + WX4 + WDT4;
    round_weights_kernel<<<(TOT4 + 255) / 256, 256>>>(
        W_in, W_x, W_dt, W_out, p_wi, p_wx, p_wdt, p_wo);

    // 1) xr = x @ W_in^T   (A = raw x, rounded in-register)
    gemm_mma<0, 0, 1><<<dim3(32, 32, 1), 128, SMEM>>>(
        x, p_wi, nullptr, p_xr, DM, DM, DM, 2 * DI);

    // 2) xs = tf32(silu(causal dwconv(xr[:, :DI])))
    conv_silu_kernel<<<(NT * DI) / 256, 256>>>(conv_w, conv_b);

    // 3) x_dbl = xs @ W_x^T  split-K=8, atomicAdd  -> [4096,96]
    gemm_mma<3, 96, 0><<<dim3(1, 32, 8), 128, SMEM>>>(
        p_xs, p_wx, nullptr, p_xdbl, DI / 8, DI, DI, 96);

    // 4) delta = softplus(x_dbl[:, :64] @ W_dt^T + b_dt)  (A rounded in-register)
    gemm_mma<1, 0, 1><<<dim3(16, 32, 1), 128, SMEM>>>(
        p_xdbl, p_wdt, b_dt, p_delta, DTR, 96, DTR, DI);

    // 5) selective scan (+D skip, *silu(res), tf32 round) -> g_yg
    scan_kernel<<<dim3(DI / SC_DPB, BB), 256>>>(A_log, Dp);

    // 6) out = yg @ W_out^T  (yg pre-rounded by scan)
    gemm_mma<0, 0, 0><<<dim3(8, 32, 1), 128, SMEM>>>(
        p_yg, p_wo, nullptr, out, DI, DI, DI, DM);
}